// round 4
// baseline (speedup 1.0000x reference)
#include <cuda_runtime.h>
#include <cuda_fp16.h>
#include <math.h>
#include <stdint.h>

#define BB   8
#define NP   2000
#define NNB  64
#define NF   19
#define HH   64
#define NNODE (BB*NP)          // 16000
#define NE   (BB*NP*NNB)       // 1024000

// ---------------- device scratch (no allocations allowed) ----------------
__device__ __half g_tbuf[(size_t)HH * NE];   // 131 MB, feature-major [j*NE + edge], reused t1->t2
__device__ float  g_pooled[NNODE * HH];      // 4 MB
__device__ float  g_zA[NNODE * HH];
__device__ float  g_zB[NNODE * HH];
__device__ float  g_colmax[BB * HH];
__device__ double g_sum1[HH], g_sq1[HH], g_sum2[HH], g_sq2[HH];
__device__ double g_U0[BB];

__device__ __forceinline__ const float* selz(int w) {
    return w == 0 ? g_pooled : (w == 1 ? g_zA : g_zB);
}

// ---------------- zero accumulators ----------------
__global__ void k_zero() {
    int t = threadIdx.x;
    if (t < HH) { g_sum1[t] = 0.0; g_sq1[t] = 0.0; g_sum2[t] = 0.0; g_sq2[t] = 0.0; }
    if (t < BB) g_U0[t] = 0.0;
}

// ---------------- stage 1: features + L0(relu) + L1, stats of t1, prior ----------------
__global__ __launch_bounds__(64) void k_edge1(
    const float* __restrict__ pos, const float* __restrict__ orR,
    const int*   __restrict__ nbr,
    const float* __restrict__ w0, const float* __restrict__ b0,
    const float* __restrict__ w1, const float* __restrict__ b1)
{
    __shared__ float w0s[HH * 32];           // padded rows for conflict-free broadcast
    __shared__ float w1s[HH * HH];
    __shared__ float b0s[HH], b1s[HH];
    __shared__ float ts[NNB][HH + 1];
    __shared__ float posi[3], Ris[9], prsh[NNB];

    const int node = blockIdx.x;             // b*NP + n
    const int b    = node / NP;
    const int m    = threadIdx.x;            // neighbor index 0..63

    for (int i = m; i < HH * HH; i += 64) w1s[i] = w1[i];
    for (int i = m; i < HH * NF; i += 64) { int j = i / NF, c = i % NF; w0s[j * 32 + c] = w0[i]; }
    b0s[m] = b0[m]; b1s[m] = b1[m];
    if (m < 3) posi[m] = pos[node * 3 + m];
    if (m < 9) Ris[m]  = orR[node * 9 + m];
    __syncthreads();

    const int jn   = nbr[node * NNB + m];
    const int nidx = b * NP + jn;

    float d0 = pos[nidx * 3 + 0] - posi[0]; d0 -= rintf(d0);   // BOX = 1
    float d1 = pos[nidx * 3 + 1] - posi[1]; d1 -= rintf(d1);
    float d2 = pos[nidx * 3 + 2] - posi[2]; d2 -= rintf(d2);
    float r2 = d0 * d0 + d1 * d1 + d2 * d2 + 1e-12f;
    float R  = sqrtf(r2);
    float inv = 1.0f / R;

    float f[NF];
    f[0] = d0 * inv; f[1] = d1 * inv; f[2] = d2 * inv; f[3] = R;

    float Rj[9];
#pragma unroll
    for (int k = 0; k < 9; k++) Rj[k] = orR[nidx * 9 + k];

#pragma unroll
    for (int j = 0; j < 3; j++) {
        f[4 + j] = f[0] * Ris[j] + f[1] * Ris[3 + j] + f[2] * Ris[6 + j];
        f[7 + j] = f[0] * Rj[j]  + f[1] * Rj[3 + j]  + f[2] * Rj[6 + j];
    }
#pragma unroll
    for (int j = 0; j < 3; j++)
#pragma unroll
        for (int k = 0; k < 3; k++)
            f[10 + j * 3 + k] = Ris[j] * Rj[k] + Ris[3 + j] * Rj[3 + k] + Ris[6 + j] * Rj[6 + k];

    // power-law prior (SIGMA/R)^12
    {
        float tp = 0.01f * inv;
        float tp2 = tp * tp, tp4 = tp2 * tp2, tp8 = tp4 * tp4;
        prsh[m] = tp8 * tp4;
    }

    // h1 = relu(W0 x + b0)
    float h1[HH];
#pragma unroll 8
    for (int j = 0; j < HH; j++) {
        float a0 = b0s[j], a1 = 0.f;
#pragma unroll
        for (int i = 0; i < 18; i += 2) {
            a0 += w0s[j * 32 + i]     * f[i];
            a1 += w0s[j * 32 + i + 1] * f[i + 1];
        }
        a0 += w0s[j * 32 + 18] * f[18];
        h1[j] = fmaxf(a0 + a1, 0.f);
    }

    // t1 = W1 h1 + b1; write scratch (fp16) + shared transpose for exact fp32 stats
    const unsigned edge = (unsigned)node * NNB + m;
#pragma unroll 8
    for (int j = 0; j < HH; j++) {
        float a0 = b1s[j], a1 = 0.f, a2 = 0.f, a3 = 0.f;
#pragma unroll
        for (int h = 0; h < HH; h += 4) {
            a0 += w1s[j * 64 + h]     * h1[h];
            a1 += w1s[j * 64 + h + 1] * h1[h + 1];
            a2 += w1s[j * 64 + h + 2] * h1[h + 2];
            a3 += w1s[j * 64 + h + 3] * h1[h + 3];
        }
        float v = (a0 + a1) + (a2 + a3);
        float vh = __half2float(__float2half_rn(v));   // store-rounded value everywhere
        ts[m][j] = vh;
        g_tbuf[(size_t)j * NE + edge] = __float2half_rn(v);
    }
    __syncthreads();

    float s = 0.f, ss = 0.f;
#pragma unroll 8
    for (int t = 0; t < NNB; t++) { float v = ts[t][m]; s += v; ss += v * v; }
    atomicAdd(&g_sum1[m], (double)s);
    atomicAdd(&g_sq1[m],  (double)ss);

    if (m == 0) {
        float ps = 0.f;
        for (int t = 0; t < NNB; t++) ps += prsh[t];
        atomicAdd(&g_U0[b], (double)ps);
    }
}

// ---------------- stage 2: BN1+relu -> L2, stats of t2 (in-place scratch) ----------------
__global__ __launch_bounds__(64) void k_edge2(
    const float* __restrict__ g1, const float* __restrict__ be1,
    const float* __restrict__ w2, const float* __restrict__ b2)
{
    __shared__ float w2s[HH * HH], b2s[HH], sc[HH], sh[HH];
    __shared__ float ts[NNB][HH + 1];

    const int node = blockIdx.x;
    const int m    = threadIdx.x;

    for (int i = m; i < HH * HH; i += 64) w2s[i] = w2[i];
    b2s[m] = b2[m];
    {
        double mean = g_sum1[m] / (double)NE;
        double var  = g_sq1[m] / (double)NE - mean * mean;
        float istd  = rsqrtf((float)var + 1e-5f);
        float scale = g1[m] * istd;
        sc[m] = scale;
        sh[m] = be1[m] - (float)mean * scale;
    }
    __syncthreads();

    const unsigned edge = (unsigned)node * NNB + m;
    float h[HH];
#pragma unroll
    for (int j = 0; j < HH; j++)
        h[j] = fmaxf(__half2float(g_tbuf[(size_t)j * NE + edge]) * sc[j] + sh[j], 0.f);

#pragma unroll 8
    for (int j = 0; j < HH; j++) {
        float a0 = b2s[j], a1 = 0.f, a2 = 0.f, a3 = 0.f;
#pragma unroll
        for (int hh = 0; hh < HH; hh += 4) {
            a0 += w2s[j * 64 + hh]     * h[hh];
            a1 += w2s[j * 64 + hh + 1] * h[hh + 1];
            a2 += w2s[j * 64 + hh + 2] * h[hh + 2];
            a3 += w2s[j * 64 + hh + 3] * h[hh + 3];
        }
        float v = (a0 + a1) + (a2 + a3);
        ts[m][j] = __half2float(__float2half_rn(v));
        g_tbuf[(size_t)j * NE + edge] = __float2half_rn(v);   // in-place: own slot only
    }
    __syncthreads();

    float s = 0.f, ss = 0.f;
#pragma unroll 8
    for (int t = 0; t < NNB; t++) { float v = ts[t][m]; s += v; ss += v * v; }
    atomicAdd(&g_sum2[m], (double)s);
    atomicAdd(&g_sq2[m],  (double)ss);
}

// ---------------- stage 3: BN2+relu -> L3 -> neighbor mean-pool ----------------
__global__ __launch_bounds__(64) void k_edge3(
    const float* __restrict__ g2, const float* __restrict__ be2,
    const float* __restrict__ w3, const float* __restrict__ b3)
{
    __shared__ float w3s[HH * HH], b3s[HH], sc[HH], sh[HH];
    __shared__ float ts[NNB][HH + 1];

    const int node = blockIdx.x;
    const int m    = threadIdx.x;

    for (int i = m; i < HH * HH; i += 64) w3s[i] = w3[i];
    b3s[m] = b3[m];
    {
        double mean = g_sum2[m] / (double)NE;
        double var  = g_sq2[m] / (double)NE - mean * mean;
        float istd  = rsqrtf((float)var + 1e-5f);
        float scale = g2[m] * istd;
        sc[m] = scale;
        sh[m] = be2[m] - (float)mean * scale;
    }
    __syncthreads();

    const unsigned edge = (unsigned)node * NNB + m;
    float h[HH];
#pragma unroll
    for (int j = 0; j < HH; j++)
        h[j] = fmaxf(__half2float(g_tbuf[(size_t)j * NE + edge]) * sc[j] + sh[j], 0.f);

#pragma unroll 8
    for (int j = 0; j < HH; j++) {
        float a0 = b3s[j], a1 = 0.f, a2 = 0.f, a3 = 0.f;
#pragma unroll
        for (int hh = 0; hh < HH; hh += 4) {
            a0 += w3s[j * 64 + hh]     * h[hh];
            a1 += w3s[j * 64 + hh + 1] * h[hh + 1];
            a2 += w3s[j * 64 + hh + 2] * h[hh + 2];
            a3 += w3s[j * 64 + hh + 3] * h[hh + 3];
        }
        ts[m][j] = (a0 + a1) + (a2 + a3);
    }
    __syncthreads();

    // mean over neighbors: thread m owns feature m
    float s = 0.f;
#pragma unroll 8
    for (int t = 0; t < NNB; t++) s += ts[t][m];
    g_pooled[node * HH + m] = s * (1.0f / NNB);
}

// ---------------- head: per-feature max over particles ----------------
__global__ __launch_bounds__(256) void k_colmax(int insel)
{
    const float* z = selz(insel);
    const int b = blockIdx.x;
    const int t = threadIdx.x;
    const int f = t & 63, g = t >> 6;        // 4 row groups x 64 features
    float mx = -INFINITY;
    for (int n = g; n < NP; n += 4)
        mx = fmaxf(mx, z[((size_t)b * NP + n) * HH + f]);
    __shared__ float red[256];
    red[t] = mx;
    __syncthreads();
    if (g == 0)
        g_colmax[b * HH + f] = fmaxf(fmaxf(red[f], red[64 + f]),
                                     fmaxf(red[128 + f], red[192 + f]));
}

// ---------------- head: PermEqui1_max block: tanh((z - zmax) W^T + b) ----------------
__global__ __launch_bounds__(256) void k_pe(int insel, int outsel,
    const float* __restrict__ w, const float* __restrict__ bias)
{
    __shared__ float ws[HH * HH], cf[HH], cms[HH];
    const int bx = blockIdx.x;
    const int b  = bx >> 3;                  // 8 row-blocks of 256 per batch
    const int rb = bx & 7;
    const int t  = threadIdx.x;
    const float* zin = selz(insel);
    float* zout = (outsel == 1) ? g_zA : g_zB;

    for (int i = t; i < HH * HH; i += 256) ws[i] = w[i];
    if (t < HH) cms[t] = g_colmax[b * HH + t];
    __syncthreads();

    if (t < HH) {
        float a0 = bias[t], a1 = 0.f, a2 = 0.f, a3 = 0.f;
#pragma unroll
        for (int h = 0; h < HH; h += 4) {
            a0 -= cms[h]     * ws[t * 64 + h];
            a1 -= cms[h + 1] * ws[t * 64 + h + 1];
            a2 -= cms[h + 2] * ws[t * 64 + h + 2];
            a3 -= cms[h + 3] * ws[t * 64 + h + 3];
        }
        cf[t] = (a0 + a1) + (a2 + a3);
    }
    __syncthreads();

    const int n = rb * 256 + t;
    if (n < NP) {
        const float* zr = &zin[((size_t)b * NP + n) * HH];
        float z[HH];
#pragma unroll
        for (int h = 0; h < HH; h++) z[h] = zr[h];
        float* orow = &zout[((size_t)b * NP + n) * HH];
#pragma unroll 4
        for (int fj = 0; fj < HH; fj++) {
            float a0 = cf[fj], a1 = 0.f, a2 = 0.f, a3 = 0.f;
#pragma unroll
            for (int h = 0; h < HH; h += 4) {
                a0 += z[h]     * ws[fj * 64 + h];
                a1 += z[h + 1] * ws[fj * 64 + h + 1];
                a2 += z[h + 2] * ws[fj * 64 + h + 2];
                a3 += z[h + 3] * ws[fj * 64 + h + 3];
            }
            orow[fj] = tanhf((a0 + a1) + (a2 + a3));
        }
    }
}

// ---------------- head: particle max-pool + 2-layer regressor + prior ----------------
__global__ __launch_bounds__(64) void k_head(int insel,
    const float* __restrict__ r1w, const float* __restrict__ r1b,
    const float* __restrict__ r2w, const float* __restrict__ r2b,
    float* __restrict__ out)
{
    const float* zin = selz(insel);
    const int b = blockIdx.x;
    const int f = threadIdx.x;
    __shared__ float s[HH], tv[HH];

    float m0 = -INFINITY, m1 = -INFINITY, m2 = -INFINITY, m3 = -INFINITY;
    for (int n = 0; n < NP; n += 4) {
        m0 = fmaxf(m0, zin[((size_t)b * NP + n)     * HH + f]);
        m1 = fmaxf(m1, zin[((size_t)b * NP + n + 1) * HH + f]);
        m2 = fmaxf(m2, zin[((size_t)b * NP + n + 2) * HH + f]);
        m3 = fmaxf(m3, zin[((size_t)b * NP + n + 3) * HH + f]);
    }
    s[f] = fmaxf(fmaxf(m0, m1), fmaxf(m2, m3));
    __syncthreads();

    float a = r1b[f];
#pragma unroll
    for (int h = 0; h < HH; h++) a += s[h] * r1w[f * 64 + h];
    tv[f] = tanhf(a);
    __syncthreads();

    if (f == 0) {
        float e = r2b[0];
        for (int h = 0; h < HH; h++) e += tv[h] * r2w[h];
        out[b] = e + (float)g_U0[b];
    }
}

// ---------------- launcher ----------------
extern "C" void kernel_launch(void* const* d_in, const int* in_sizes, int n_in,
                              void* d_out, int out_size)
{
    const float* pos = (const float*)d_in[0];
    const float* orR = (const float*)d_in[1];
    const int*   nbr = (const int*)  d_in[2];
    const float* w0  = (const float*)d_in[3];
    const float* b0  = (const float*)d_in[4];
    const float* w1  = (const float*)d_in[5];
    const float* b1  = (const float*)d_in[6];
    const float* g1  = (const float*)d_in[7];
    const float* be1 = (const float*)d_in[8];
    const float* w2  = (const float*)d_in[9];
    const float* b2  = (const float*)d_in[10];
    const float* g2  = (const float*)d_in[11];
    const float* be2 = (const float*)d_in[12];
    const float* w3  = (const float*)d_in[13];
    const float* b3  = (const float*)d_in[14];
    const float* p1w = (const float*)d_in[15];
    const float* p1b = (const float*)d_in[16];
    const float* p2w = (const float*)d_in[17];
    const float* p2b = (const float*)d_in[18];
    const float* p3w = (const float*)d_in[19];
    const float* p3b = (const float*)d_in[20];
    const float* r1w = (const float*)d_in[21];
    const float* r1b = (const float*)d_in[22];
    const float* r2w = (const float*)d_in[23];
    const float* r2b = (const float*)d_in[24];
    float* out = (float*)d_out;

    k_zero <<<1, 64>>>();
    k_edge1<<<NNODE, 64>>>(pos, orR, nbr, w0, b0, w1, b1);
    k_edge2<<<NNODE, 64>>>(g1, be1, w2, b2);
    k_edge3<<<NNODE, 64>>>(g2, be2, w3, b3);
    k_colmax<<<BB, 256>>>(0);
    k_pe   <<<64, 256>>>(0, 1, p1w, p1b);
    k_colmax<<<BB, 256>>>(1);
    k_pe   <<<64, 256>>>(1, 2, p2w, p2b);
    k_colmax<<<BB, 256>>>(2);
    k_pe   <<<64, 256>>>(2, 1, p3w, p3b);
    k_head <<<BB, 64>>>(1, r1w, r1b, r2w, r2b, out);
}

// round 5
// speedup vs baseline: 1.0001x; 1.0001x over previous
#include <cuda_runtime.h>
#include <cuda_fp16.h>
#include <math.h>
#include <stdint.h>

#define BB   8
#define NP   2000
#define NNB  64
#define NF   19
#define HH   64
#define NNODE (BB*NP)          // 16000
#define NE   (BB*NP*NNB)       // 1024000

// ---------------- device scratch (no allocations allowed) ----------------
__device__ __half g_tbuf[(size_t)HH * NE];   // 131 MB, feature-major [j*NE + edge], reused t1->t2
__device__ float  g_pooled[NNODE * HH];      // 4 MB
__device__ float  g_zA[NNODE * HH];
__device__ float  g_zB[NNODE * HH];
__device__ float  g_colmax[BB * HH];
__device__ double g_sum1[HH], g_sq1[HH], g_sum2[HH], g_sq2[HH];
__device__ double g_U0[BB];

__device__ __forceinline__ const float* selz(int w) {
    return w == 0 ? g_pooled : (w == 1 ? g_zA : g_zB);
}

// ---------------- zero accumulators ----------------
__global__ void k_zero() {
    int t = threadIdx.x;
    if (t < HH) { g_sum1[t] = 0.0; g_sq1[t] = 0.0; g_sum2[t] = 0.0; g_sq2[t] = 0.0; }
    if (t < BB) g_U0[t] = 0.0;
}

// ---------------- stage 1: features + L0(relu) + L1, stats of t1, prior ----------------
__global__ __launch_bounds__(64) void k_edge1(
    const float* __restrict__ pos, const float* __restrict__ orR,
    const int*   __restrict__ nbr,
    const float* __restrict__ w0, const float* __restrict__ b0,
    const float* __restrict__ w1, const float* __restrict__ b1)
{
    __shared__ float w0s[HH * 32];           // padded rows for conflict-free broadcast
    __shared__ float w1s[HH * HH];
    __shared__ float b0s[HH], b1s[HH];
    __shared__ float ts[NNB][HH + 1];
    __shared__ float posi[3], Ris[9], prsh[NNB];

    const int node = blockIdx.x;             // b*NP + n
    const int b    = node / NP;
    const int m    = threadIdx.x;            // neighbor index 0..63

    for (int i = m; i < HH * HH; i += 64) w1s[i] = w1[i];
    for (int i = m; i < HH * NF; i += 64) { int j = i / NF, c = i % NF; w0s[j * 32 + c] = w0[i]; }
    b0s[m] = b0[m]; b1s[m] = b1[m];
    if (m < 3) posi[m] = pos[node * 3 + m];
    if (m < 9) Ris[m]  = orR[node * 9 + m];
    __syncthreads();

    const int jn   = nbr[node * NNB + m];
    const int nidx = b * NP + jn;

    float d0 = pos[nidx * 3 + 0] - posi[0]; d0 -= rintf(d0);   // BOX = 1
    float d1 = pos[nidx * 3 + 1] - posi[1]; d1 -= rintf(d1);
    float d2 = pos[nidx * 3 + 2] - posi[2]; d2 -= rintf(d2);
    float r2 = d0 * d0 + d1 * d1 + d2 * d2 + 1e-12f;
    float R  = sqrtf(r2);
    float inv = 1.0f / R;

    float f[NF];
    f[0] = d0 * inv; f[1] = d1 * inv; f[2] = d2 * inv; f[3] = R;

    float Rj[9];
#pragma unroll
    for (int k = 0; k < 9; k++) Rj[k] = orR[nidx * 9 + k];

#pragma unroll
    for (int j = 0; j < 3; j++) {
        f[4 + j] = f[0] * Ris[j] + f[1] * Ris[3 + j] + f[2] * Ris[6 + j];
        f[7 + j] = f[0] * Rj[j]  + f[1] * Rj[3 + j]  + f[2] * Rj[6 + j];
    }
#pragma unroll
    for (int j = 0; j < 3; j++)
#pragma unroll
        for (int k = 0; k < 3; k++)
            f[10 + j * 3 + k] = Ris[j] * Rj[k] + Ris[3 + j] * Rj[3 + k] + Ris[6 + j] * Rj[6 + k];

    // power-law prior (SIGMA/R)^12
    {
        float tp = 0.01f * inv;
        float tp2 = tp * tp, tp4 = tp2 * tp2, tp8 = tp4 * tp4;
        prsh[m] = tp8 * tp4;
    }

    // h1 = relu(W0 x + b0)
    float h1[HH];
#pragma unroll 8
    for (int j = 0; j < HH; j++) {
        float a0 = b0s[j], a1 = 0.f;
#pragma unroll
        for (int i = 0; i < 18; i += 2) {
            a0 += w0s[j * 32 + i]     * f[i];
            a1 += w0s[j * 32 + i + 1] * f[i + 1];
        }
        a0 += w0s[j * 32 + 18] * f[18];
        h1[j] = fmaxf(a0 + a1, 0.f);
    }

    // t1 = W1 h1 + b1; write scratch (fp16) + shared transpose for exact fp32 stats
    const unsigned edge = (unsigned)node * NNB + m;
#pragma unroll 8
    for (int j = 0; j < HH; j++) {
        float a0 = b1s[j], a1 = 0.f, a2 = 0.f, a3 = 0.f;
#pragma unroll
        for (int h = 0; h < HH; h += 4) {
            a0 += w1s[j * 64 + h]     * h1[h];
            a1 += w1s[j * 64 + h + 1] * h1[h + 1];
            a2 += w1s[j * 64 + h + 2] * h1[h + 2];
            a3 += w1s[j * 64 + h + 3] * h1[h + 3];
        }
        float v = (a0 + a1) + (a2 + a3);
        float vh = __half2float(__float2half_rn(v));   // store-rounded value everywhere
        ts[m][j] = vh;
        g_tbuf[(size_t)j * NE + edge] = __float2half_rn(v);
    }
    __syncthreads();

    float s = 0.f, ss = 0.f;
#pragma unroll 8
    for (int t = 0; t < NNB; t++) { float v = ts[t][m]; s += v; ss += v * v; }
    atomicAdd(&g_sum1[m], (double)s);
    atomicAdd(&g_sq1[m],  (double)ss);

    if (m == 0) {
        float ps = 0.f;
        for (int t = 0; t < NNB; t++) ps += prsh[t];
        atomicAdd(&g_U0[b], (double)ps);
    }
}

// ---------------- stage 2: BN1+relu -> L2, stats of t2 (in-place scratch) ----------------
__global__ __launch_bounds__(64) void k_edge2(
    const float* __restrict__ g1, const float* __restrict__ be1,
    const float* __restrict__ w2, const float* __restrict__ b2)
{
    __shared__ float w2s[HH * HH], b2s[HH], sc[HH], sh[HH];
    __shared__ float ts[NNB][HH + 1];

    const int node = blockIdx.x;
    const int m    = threadIdx.x;

    for (int i = m; i < HH * HH; i += 64) w2s[i] = w2[i];
    b2s[m] = b2[m];
    {
        double mean = g_sum1[m] / (double)NE;
        double var  = g_sq1[m] / (double)NE - mean * mean;
        float istd  = rsqrtf((float)var + 1e-5f);
        float scale = g1[m] * istd;
        sc[m] = scale;
        sh[m] = be1[m] - (float)mean * scale;
    }
    __syncthreads();

    const unsigned edge = (unsigned)node * NNB + m;
    float h[HH];
#pragma unroll
    for (int j = 0; j < HH; j++)
        h[j] = fmaxf(__half2float(g_tbuf[(size_t)j * NE + edge]) * sc[j] + sh[j], 0.f);

#pragma unroll 8
    for (int j = 0; j < HH; j++) {
        float a0 = b2s[j], a1 = 0.f, a2 = 0.f, a3 = 0.f;
#pragma unroll
        for (int hh = 0; hh < HH; hh += 4) {
            a0 += w2s[j * 64 + hh]     * h[hh];
            a1 += w2s[j * 64 + hh + 1] * h[hh + 1];
            a2 += w2s[j * 64 + hh + 2] * h[hh + 2];
            a3 += w2s[j * 64 + hh + 3] * h[hh + 3];
        }
        float v = (a0 + a1) + (a2 + a3);
        ts[m][j] = __half2float(__float2half_rn(v));
        g_tbuf[(size_t)j * NE + edge] = __float2half_rn(v);   // in-place: own slot only
    }
    __syncthreads();

    float s = 0.f, ss = 0.f;
#pragma unroll 8
    for (int t = 0; t < NNB; t++) { float v = ts[t][m]; s += v; ss += v * v; }
    atomicAdd(&g_sum2[m], (double)s);
    atomicAdd(&g_sq2[m],  (double)ss);
}

// ---------------- stage 3: BN2+relu -> L3 -> neighbor mean-pool ----------------
__global__ __launch_bounds__(64) void k_edge3(
    const float* __restrict__ g2, const float* __restrict__ be2,
    const float* __restrict__ w3, const float* __restrict__ b3)
{
    __shared__ float w3s[HH * HH], b3s[HH], sc[HH], sh[HH];
    __shared__ float ts[NNB][HH + 1];

    const int node = blockIdx.x;
    const int m    = threadIdx.x;

    for (int i = m; i < HH * HH; i += 64) w3s[i] = w3[i];
    b3s[m] = b3[m];
    {
        double mean = g_sum2[m] / (double)NE;
        double var  = g_sq2[m] / (double)NE - mean * mean;
        float istd  = rsqrtf((float)var + 1e-5f);
        float scale = g2[m] * istd;
        sc[m] = scale;
        sh[m] = be2[m] - (float)mean * scale;
    }
    __syncthreads();

    const unsigned edge = (unsigned)node * NNB + m;
    float h[HH];
#pragma unroll
    for (int j = 0; j < HH; j++)
        h[j] = fmaxf(__half2float(g_tbuf[(size_t)j * NE + edge]) * sc[j] + sh[j], 0.f);

#pragma unroll 8
    for (int j = 0; j < HH; j++) {
        float a0 = b3s[j], a1 = 0.f, a2 = 0.f, a3 = 0.f;
#pragma unroll
        for (int hh = 0; hh < HH; hh += 4) {
            a0 += w3s[j * 64 + hh]     * h[hh];
            a1 += w3s[j * 64 + hh + 1] * h[hh + 1];
            a2 += w3s[j * 64 + hh + 2] * h[hh + 2];
            a3 += w3s[j * 64 + hh + 3] * h[hh + 3];
        }
        ts[m][j] = (a0 + a1) + (a2 + a3);
    }
    __syncthreads();

    // mean over neighbors: thread m owns feature m
    float s = 0.f;
#pragma unroll 8
    for (int t = 0; t < NNB; t++) s += ts[t][m];
    g_pooled[node * HH + m] = s * (1.0f / NNB);
}

// ---------------- head: per-feature max over particles ----------------
__global__ __launch_bounds__(256) void k_colmax(int insel)
{
    const float* z = selz(insel);
    const int b = blockIdx.x;
    const int t = threadIdx.x;
    const int f = t & 63, g = t >> 6;        // 4 row groups x 64 features
    float mx = -INFINITY;
    for (int n = g; n < NP; n += 4)
        mx = fmaxf(mx, z[((size_t)b * NP + n) * HH + f]);
    __shared__ float red[256];
    red[t] = mx;
    __syncthreads();
    if (g == 0)
        g_colmax[b * HH + f] = fmaxf(fmaxf(red[f], red[64 + f]),
                                     fmaxf(red[128 + f], red[192 + f]));
}

// ---------------- head: PermEqui1_max block: tanh((z - zmax) W^T + b) ----------------
__global__ __launch_bounds__(256) void k_pe(int insel, int outsel,
    const float* __restrict__ w, const float* __restrict__ bias)
{
    __shared__ float ws[HH * HH], cf[HH], cms[HH];
    const int bx = blockIdx.x;
    const int b  = bx >> 3;                  // 8 row-blocks of 256 per batch
    const int rb = bx & 7;
    const int t  = threadIdx.x;
    const float* zin = selz(insel);
    float* zout = (outsel == 1) ? g_zA : g_zB;

    for (int i = t; i < HH * HH; i += 256) ws[i] = w[i];
    if (t < HH) cms[t] = g_colmax[b * HH + t];
    __syncthreads();

    if (t < HH) {
        float a0 = bias[t], a1 = 0.f, a2 = 0.f, a3 = 0.f;
#pragma unroll
        for (int h = 0; h < HH; h += 4) {
            a0 -= cms[h]     * ws[t * 64 + h];
            a1 -= cms[h + 1] * ws[t * 64 + h + 1];
            a2 -= cms[h + 2] * ws[t * 64 + h + 2];
            a3 -= cms[h + 3] * ws[t * 64 + h + 3];
        }
        cf[t] = (a0 + a1) + (a2 + a3);
    }
    __syncthreads();

    const int n = rb * 256 + t;
    if (n < NP) {
        const float* zr = &zin[((size_t)b * NP + n) * HH];
        float z[HH];
#pragma unroll
        for (int h = 0; h < HH; h++) z[h] = zr[h];
        float* orow = &zout[((size_t)b * NP + n) * HH];
#pragma unroll 4
        for (int fj = 0; fj < HH; fj++) {
            float a0 = cf[fj], a1 = 0.f, a2 = 0.f, a3 = 0.f;
#pragma unroll
            for (int h = 0; h < HH; h += 4) {
                a0 += z[h]     * ws[fj * 64 + h];
                a1 += z[h + 1] * ws[fj * 64 + h + 1];
                a2 += z[h + 2] * ws[fj * 64 + h + 2];
                a3 += z[h + 3] * ws[fj * 64 + h + 3];
            }
            orow[fj] = tanhf((a0 + a1) + (a2 + a3));
        }
    }
}

// ---------------- head: particle max-pool + 2-layer regressor + prior ----------------
__global__ __launch_bounds__(64) void k_head(int insel,
    const float* __restrict__ r1w, const float* __restrict__ r1b,
    const float* __restrict__ r2w, const float* __restrict__ r2b,
    float* __restrict__ out)
{
    const float* zin = selz(insel);
    const int b = blockIdx.x;
    const int f = threadIdx.x;
    __shared__ float s[HH], tv[HH];

    float m0 = -INFINITY, m1 = -INFINITY, m2 = -INFINITY, m3 = -INFINITY;
    for (int n = 0; n < NP; n += 4) {
        m0 = fmaxf(m0, zin[((size_t)b * NP + n)     * HH + f]);
        m1 = fmaxf(m1, zin[((size_t)b * NP + n + 1) * HH + f]);
        m2 = fmaxf(m2, zin[((size_t)b * NP + n + 2) * HH + f]);
        m3 = fmaxf(m3, zin[((size_t)b * NP + n + 3) * HH + f]);
    }
    s[f] = fmaxf(fmaxf(m0, m1), fmaxf(m2, m3));
    __syncthreads();

    float a = r1b[f];
#pragma unroll
    for (int h = 0; h < HH; h++) a += s[h] * r1w[f * 64 + h];
    tv[f] = tanhf(a);
    __syncthreads();

    if (f == 0) {
        float e = r2b[0];
        for (int h = 0; h < HH; h++) e += tv[h] * r2w[h];
        out[b] = e + (float)g_U0[b];
    }
}

// ---------------- launcher ----------------
extern "C" void kernel_launch(void* const* d_in, const int* in_sizes, int n_in,
                              void* d_out, int out_size)
{
    const float* pos = (const float*)d_in[0];
    const float* orR = (const float*)d_in[1];
    const int*   nbr = (const int*)  d_in[2];
    const float* w0  = (const float*)d_in[3];
    const float* b0  = (const float*)d_in[4];
    const float* w1  = (const float*)d_in[5];
    const float* b1  = (const float*)d_in[6];
    const float* g1  = (const float*)d_in[7];
    const float* be1 = (const float*)d_in[8];
    const float* w2  = (const float*)d_in[9];
    const float* b2  = (const float*)d_in[10];
    const float* g2  = (const float*)d_in[11];
    const float* be2 = (const float*)d_in[12];
    const float* w3  = (const float*)d_in[13];
    const float* b3  = (const float*)d_in[14];
    const float* p1w = (const float*)d_in[15];
    const float* p1b = (const float*)d_in[16];
    const float* p2w = (const float*)d_in[17];
    const float* p2b = (const float*)d_in[18];
    const float* p3w = (const float*)d_in[19];
    const float* p3b = (const float*)d_in[20];
    const float* r1w = (const float*)d_in[21];
    const float* r1b = (const float*)d_in[22];
    const float* r2w = (const float*)d_in[23];
    const float* r2b = (const float*)d_in[24];
    float* out = (float*)d_out;

    k_zero <<<1, 64>>>();
    k_edge1<<<NNODE, 64>>>(pos, orR, nbr, w0, b0, w1, b1);
    k_edge2<<<NNODE, 64>>>(g1, be1, w2, b2);
    k_edge3<<<NNODE, 64>>>(g2, be2, w3, b3);
    k_colmax<<<BB, 256>>>(0);
    k_pe   <<<64, 256>>>(0, 1, p1w, p1b);
    k_colmax<<<BB, 256>>>(1);
    k_pe   <<<64, 256>>>(1, 2, p2w, p2b);
    k_colmax<<<BB, 256>>>(2);
    k_pe   <<<64, 256>>>(2, 1, p3w, p3b);
    k_head <<<BB, 64>>>(1, r1w, r1b, r2w, r2b, out);
}

// round 6
// speedup vs baseline: 1.1277x; 1.1276x over previous
#include <cuda_runtime.h>
#include <cuda_fp16.h>
#include <math.h>
#include <stdint.h>

#define BB   8
#define NP   2000
#define NNB  64
#define NF   19
#define HH   64
#define NNODE (BB*NP)          // 16000
#define NE   (BB*NP*NNB)       // 1024000

// ---------------- device scratch ----------------
__device__ __half g_tbuf[(size_t)NE * HH];   // 131 MB, ROW-major [edge][j]
__device__ float  g_pooled[NNODE * HH];
__device__ float  g_zA[NNODE * HH];
__device__ float  g_zB[NNODE * HH];
__device__ float  g_colmax[BB * HH];
__device__ double g_sum1[HH], g_sq1[HH], g_sum2[HH], g_sq2[HH];
__device__ double g_U0[BB];

__device__ __forceinline__ const float* selz(int w) {
    return w == 0 ? g_pooled : (w == 1 ? g_zA : g_zB);
}

// ---- packed f32x2 helpers ----
__device__ __forceinline__ unsigned long long pk2(float x) {
    unsigned long long r;
    asm("mov.b64 %0, {%1, %1};" : "=l"(r) : "f"(x));
    return r;
}
__device__ __forceinline__ unsigned long long pkab(float a, float b) {
    unsigned long long r;
    asm("mov.b64 %0, {%1, %2};" : "=l"(r) : "f"(a), "f"(b));
    return r;
}
__device__ __forceinline__ float2 upk(unsigned long long v) {
    float2 r;
    asm("mov.b64 {%0, %1}, %2;" : "=f"(r.x), "=f"(r.y) : "l"(v));
    return r;
}
#define FMA2(d, a, b) asm("fma.rn.f32x2 %0, %1, %2, %0;" : "+l"(d) : "l"(a), "l"(b))

// ---------------- zero accumulators ----------------
__global__ void k_zero() {
    int t = threadIdx.x;
    if (t < HH) { g_sum1[t] = 0.0; g_sq1[t] = 0.0; g_sum2[t] = 0.0; g_sq2[t] = 0.0; }
    if (t < BB) g_U0[t] = 0.0;
}

// 8x8-tiled 64x64x64 GEMM core: HsT[k*64+m] x Wt[k*64+j] -> acc pairs
// caller provides acc[8][4] initialized with bias pairs.
__device__ __forceinline__ void gemm_tile(
    const float* __restrict__ HsT, const float* __restrict__ Wt,
    int m0, int j0, unsigned long long acc[8][4])
{
#pragma unroll 4
    for (int k = 0; k < 64; k++) {
        const float4 ha = *(const float4*)&HsT[k * 64 + m0];
        const float4 hb = *(const float4*)&HsT[k * 64 + m0 + 4];
        const ulonglong2 wA = *(const ulonglong2*)&Wt[k * 64 + j0];
        const ulonglong2 wB = *(const ulonglong2*)&Wt[k * 64 + j0 + 4];
        unsigned long long h;
        h = pk2(ha.x); FMA2(acc[0][0], h, wA.x); FMA2(acc[0][1], h, wA.y); FMA2(acc[0][2], h, wB.x); FMA2(acc[0][3], h, wB.y);
        h = pk2(ha.y); FMA2(acc[1][0], h, wA.x); FMA2(acc[1][1], h, wA.y); FMA2(acc[1][2], h, wB.x); FMA2(acc[1][3], h, wB.y);
        h = pk2(ha.z); FMA2(acc[2][0], h, wA.x); FMA2(acc[2][1], h, wA.y); FMA2(acc[2][2], h, wB.x); FMA2(acc[2][3], h, wB.y);
        h = pk2(ha.w); FMA2(acc[3][0], h, wA.x); FMA2(acc[3][1], h, wA.y); FMA2(acc[3][2], h, wB.x); FMA2(acc[3][3], h, wB.y);
        h = pk2(hb.x); FMA2(acc[4][0], h, wA.x); FMA2(acc[4][1], h, wA.y); FMA2(acc[4][2], h, wB.x); FMA2(acc[4][3], h, wB.y);
        h = pk2(hb.y); FMA2(acc[5][0], h, wA.x); FMA2(acc[5][1], h, wA.y); FMA2(acc[5][2], h, wB.x); FMA2(acc[5][3], h, wB.y);
        h = pk2(hb.z); FMA2(acc[6][0], h, wA.x); FMA2(acc[6][1], h, wA.y); FMA2(acc[6][2], h, wB.x); FMA2(acc[6][3], h, wB.y);
        h = pk2(hb.w); FMA2(acc[7][0], h, wA.x); FMA2(acc[7][1], h, wA.y); FMA2(acc[7][2], h, wB.x); FMA2(acc[7][3], h, wB.y);
    }
}

// load w (row-major [j][k], 64x64) coalesced into tmp (65-padded rows), then Wt[k*64+j]
__device__ __forceinline__ void stage_wT(const float* __restrict__ w,
                                         float* __restrict__ tmp65,
                                         float* __restrict__ Wt, int t)
{
    for (int idx = t; idx < 4096; idx += 64)
        tmp65[(idx >> 6) * 65 + (idx & 63)] = w[idx];
    __syncthreads();
#pragma unroll 8
    for (int k = 0; k < 64; k++)
        Wt[k * 64 + t] = tmp65[t * 65 + k];
    __syncthreads();
}

// ---------------- stage 1: features + L0(relu) + L1 (tiled), stats, prior ----------------
__global__ __launch_bounds__(64) void k_edge1(
    const float* __restrict__ pos, const float* __restrict__ orR,
    const int*   __restrict__ nbr,
    const float* __restrict__ w0, const float* __restrict__ b0,
    const float* __restrict__ w1, const float* __restrict__ b1)
{
    __shared__ float w0s[HH * 32];
    __shared__ float HsT[64 * 65];        // tmp(65-pad) alias, then HsT[k*64+m]
    __shared__ float Wt[64 * 64];
    __shared__ float b0s[HH], b1s[HH];
    __shared__ float psum[8 * 66], psq[8 * 66];
    __shared__ float prsh[NNB];
    __shared__ float posi[3], Ris[9];

    const int node = blockIdx.x;
    const int b    = node / NP;
    const int t    = threadIdx.x;

    for (int i = t; i < HH * NF; i += 64) { int j = i / NF, c = i % NF; w0s[j * 32 + c] = w0[i]; }
    b0s[t] = b0[t]; b1s[t] = b1[t];
    if (t < 3) posi[t] = pos[node * 3 + t];
    if (t < 9) Ris[t]  = orR[node * 9 + t];
    stage_wT(w1, HsT, Wt, t);   // includes the syncthreads that also covers w0s/posi

    // ---- phase A: thread t = edge m ----
    const int jn   = nbr[node * NNB + t];
    const int nidx = b * NP + jn;

    float d0 = pos[nidx * 3 + 0] - posi[0]; d0 -= rintf(d0);
    float d1 = pos[nidx * 3 + 1] - posi[1]; d1 -= rintf(d1);
    float d2 = pos[nidx * 3 + 2] - posi[2]; d2 -= rintf(d2);
    float r2 = d0 * d0 + d1 * d1 + d2 * d2 + 1e-12f;
    float R  = sqrtf(r2);
    float inv = 1.0f / R;

    float f[NF];
    f[0] = d0 * inv; f[1] = d1 * inv; f[2] = d2 * inv; f[3] = R;

    float Rj[9];
#pragma unroll
    for (int k = 0; k < 9; k++) Rj[k] = orR[nidx * 9 + k];
#pragma unroll
    for (int j = 0; j < 3; j++) {
        f[4 + j] = f[0] * Ris[j] + f[1] * Ris[3 + j] + f[2] * Ris[6 + j];
        f[7 + j] = f[0] * Rj[j]  + f[1] * Rj[3 + j]  + f[2] * Rj[6 + j];
    }
#pragma unroll
    for (int j = 0; j < 3; j++)
#pragma unroll
        for (int k = 0; k < 3; k++)
            f[10 + j * 3 + k] = Ris[j] * Rj[k] + Ris[3 + j] * Rj[3 + k] + Ris[6 + j] * Rj[6 + k];

    {
        float tp = 0.01f * inv;
        float tp2 = tp * tp, tp4 = tp2 * tp2, tp8 = tp4 * tp4;
        prsh[t] = tp8 * tp4;
    }

    // h1 = relu(W0 x + b0): per-thread scalar, write column t of HsT
#pragma unroll 8
    for (int j = 0; j < HH; j++) {
        float a0 = b0s[j], a1 = 0.f;
#pragma unroll
        for (int i = 0; i < 18; i += 2) {
            a0 += w0s[j * 32 + i]     * f[i];
            a1 += w0s[j * 32 + i + 1] * f[i + 1];
        }
        a0 += w0s[j * 32 + 18] * f[18];
        HsT[j * 64 + t] = fmaxf(a0 + a1, 0.f);
    }
    __syncthreads();

    // ---- tiled GEMM: t1 = h1 * W1^T + b1 ----
    const int tm = t >> 3, tj = t & 7;
    const int m0 = tm * 8, j0 = tj * 8;
    unsigned long long acc[8][4];
    {
        unsigned long long bp[4];
#pragma unroll
        for (int p = 0; p < 4; p++) bp[p] = pkab(b1s[j0 + 2 * p], b1s[j0 + 2 * p + 1]);
#pragma unroll
        for (int i = 0; i < 8; i++)
#pragma unroll
            for (int p = 0; p < 4; p++) acc[i][p] = bp[p];
    }
    gemm_tile(HsT, Wt, m0, j0, acc);

    // epilogue: fp16 store (row-major) + stats partials on rounded values
    float sj[8] = {0,0,0,0,0,0,0,0}, qj[8] = {0,0,0,0,0,0,0,0};
#pragma unroll
    for (int i = 0; i < 8; i++) {
        __half2 o[4];
#pragma unroll
        for (int p = 0; p < 4; p++) {
            float2 v = upk(acc[i][p]);
            __half2 hh = __floats2half2_rn(v.x, v.y);
            o[p] = hh;
            float2 vr = __half22float2(hh);
            sj[2*p]   += vr.x; qj[2*p]   += vr.x * vr.x;
            sj[2*p+1] += vr.y; qj[2*p+1] += vr.y * vr.y;
        }
        *(uint4*)&g_tbuf[((size_t)node * 64 + m0 + i) * 64 + j0] = *(uint4*)o;
    }
#pragma unroll
    for (int jj = 0; jj < 8; jj++) {
        psum[tm * 66 + j0 + jj] = sj[jj];
        psq [tm * 66 + j0 + jj] = qj[jj];
    }
    __syncthreads();

    float s = 0.f, q = 0.f;
#pragma unroll
    for (int r = 0; r < 8; r++) { s += psum[r * 66 + t]; q += psq[r * 66 + t]; }
    atomicAdd(&g_sum1[t], (double)s);
    atomicAdd(&g_sq1[t],  (double)q);

    if (t == 0) {
        float ps = 0.f;
        for (int r = 0; r < NNB; r++) ps += prsh[r];
        atomicAdd(&g_U0[b], (double)ps);
    }
}

// ---------------- stage 2: BN1+relu -> L2 (tiled), stats ----------------
__global__ __launch_bounds__(64) void k_edge2(
    const float* __restrict__ g1, const float* __restrict__ be1,
    const float* __restrict__ w2, const float* __restrict__ b2)
{
    __shared__ float HsT[64 * 65];
    __shared__ float Wt[64 * 64];
    __shared__ float b2s[HH], sc[HH], sh[HH];
    __shared__ float psum[8 * 66], psq[8 * 66];

    const int node = blockIdx.x;
    const int t    = threadIdx.x;

    b2s[t] = b2[t];
    {
        double mean = g_sum1[t] / (double)NE;
        double var  = g_sq1[t] / (double)NE - mean * mean;
        float istd  = rsqrtf((float)var + 1e-5f);
        float scale = g1[t] * istd;
        sc[t] = scale;
        sh[t] = be1[t] - (float)mean * scale;
    }
    stage_wT(w2, HsT, Wt, t);

    // phase A: thread t = edge m; read contiguous fp16 row, BN+relu, write column
    {
        const __half2* rowp = (const __half2*)(g_tbuf + ((size_t)node * 64 + t) * 64);
#pragma unroll 8
        for (int j2 = 0; j2 < 32; j2++) {
            float2 v = __half22float2(rowp[j2]);
            int j = 2 * j2;
            HsT[j * 64 + t]       = fmaxf(v.x * sc[j] + sh[j], 0.f);
            HsT[(j + 1) * 64 + t] = fmaxf(v.y * sc[j + 1] + sh[j + 1], 0.f);
        }
    }
    __syncthreads();

    const int tm = t >> 3, tj = t & 7;
    const int m0 = tm * 8, j0 = tj * 8;
    unsigned long long acc[8][4];
    {
        unsigned long long bp[4];
#pragma unroll
        for (int p = 0; p < 4; p++) bp[p] = pkab(b2s[j0 + 2 * p], b2s[j0 + 2 * p + 1]);
#pragma unroll
        for (int i = 0; i < 8; i++)
#pragma unroll
            for (int p = 0; p < 4; p++) acc[i][p] = bp[p];
    }
    gemm_tile(HsT, Wt, m0, j0, acc);

    float sj[8] = {0,0,0,0,0,0,0,0}, qj[8] = {0,0,0,0,0,0,0,0};
#pragma unroll
    for (int i = 0; i < 8; i++) {
        __half2 o[4];
#pragma unroll
        for (int p = 0; p < 4; p++) {
            float2 v = upk(acc[i][p]);
            __half2 hh = __floats2half2_rn(v.x, v.y);
            o[p] = hh;
            float2 vr = __half22float2(hh);
            sj[2*p]   += vr.x; qj[2*p]   += vr.x * vr.x;
            sj[2*p+1] += vr.y; qj[2*p+1] += vr.y * vr.y;
        }
        *(uint4*)&g_tbuf[((size_t)node * 64 + m0 + i) * 64 + j0] = *(uint4*)o;
    }
#pragma unroll
    for (int jj = 0; jj < 8; jj++) {
        psum[tm * 66 + j0 + jj] = sj[jj];
        psq [tm * 66 + j0 + jj] = qj[jj];
    }
    __syncthreads();

    float s = 0.f, q = 0.f;
#pragma unroll
    for (int r = 0; r < 8; r++) { s += psum[r * 66 + t]; q += psq[r * 66 + t]; }
    atomicAdd(&g_sum2[t], (double)s);
    atomicAdd(&g_sq2[t],  (double)q);
}

// ---------------- stage 3: BN2+relu -> L3 (tiled) -> neighbor mean-pool ----------------
__global__ __launch_bounds__(64) void k_edge3(
    const float* __restrict__ g2, const float* __restrict__ be2,
    const float* __restrict__ w3, const float* __restrict__ b3)
{
    __shared__ float HsT[64 * 65];
    __shared__ float Wt[64 * 64];
    __shared__ float b3s[HH], sc[HH], sh[HH];
    __shared__ float psum[8 * 66];

    const int node = blockIdx.x;
    const int t    = threadIdx.x;

    b3s[t] = b3[t];
    {
        double mean = g_sum2[t] / (double)NE;
        double var  = g_sq2[t] / (double)NE - mean * mean;
        float istd  = rsqrtf((float)var + 1e-5f);
        float scale = g2[t] * istd;
        sc[t] = scale;
        sh[t] = be2[t] - (float)mean * scale;
    }
    stage_wT(w3, HsT, Wt, t);

    {
        const __half2* rowp = (const __half2*)(g_tbuf + ((size_t)node * 64 + t) * 64);
#pragma unroll 8
        for (int j2 = 0; j2 < 32; j2++) {
            float2 v = __half22float2(rowp[j2]);
            int j = 2 * j2;
            HsT[j * 64 + t]       = fmaxf(v.x * sc[j] + sh[j], 0.f);
            HsT[(j + 1) * 64 + t] = fmaxf(v.y * sc[j + 1] + sh[j + 1], 0.f);
        }
    }
    __syncthreads();

    const int tm = t >> 3, tj = t & 7;
    const int m0 = tm * 8, j0 = tj * 8;
    unsigned long long acc[8][4];
    {
        unsigned long long bp[4];
#pragma unroll
        for (int p = 0; p < 4; p++) bp[p] = pkab(b3s[j0 + 2 * p], b3s[j0 + 2 * p + 1]);
#pragma unroll
        for (int i = 0; i < 8; i++)
#pragma unroll
            for (int p = 0; p < 4; p++) acc[i][p] = bp[p];
    }
    gemm_tile(HsT, Wt, m0, j0, acc);

    // partial mean over this thread's 8 m rows
    float sj[8] = {0,0,0,0,0,0,0,0};
#pragma unroll
    for (int i = 0; i < 8; i++)
#pragma unroll
        for (int p = 0; p < 4; p++) {
            float2 v = upk(acc[i][p]);
            sj[2*p] += v.x; sj[2*p+1] += v.y;
        }
#pragma unroll
    for (int jj = 0; jj < 8; jj++) psum[tm * 66 + j0 + jj] = sj[jj];
    __syncthreads();

    float s = 0.f;
#pragma unroll
    for (int r = 0; r < 8; r++) s += psum[r * 66 + t];
    g_pooled[node * HH + t] = s * (1.0f / NNB);
}

// ---------------- per-feature max over particles (1024 threads) ----------------
__global__ __launch_bounds__(1024) void k_colmax(int insel)
{
    const float* z = selz(insel);
    const int b = blockIdx.x;
    const int t = threadIdx.x;
    const int f = t & 63, g = t >> 6;        // 16 row groups x 64 features
    float mx = -INFINITY;
    for (int n = g; n < NP; n += 16)
        mx = fmaxf(mx, z[((size_t)b * NP + n) * HH + f]);
    __shared__ float red[1024];
    red[t] = mx;
    __syncthreads();
    if (g == 0) {
        float v = red[f];
#pragma unroll
        for (int r = 1; r < 16; r++) v = fmaxf(v, red[r * 64 + f]);
        g_colmax[b * HH + f] = v;
    }
}

// ---------------- PermEqui1_max: tanh((z - zmax) W^T + b) ----------------
__global__ __launch_bounds__(256) void k_pe(int insel, int outsel,
    const float* __restrict__ w, const float* __restrict__ bias)
{
    __shared__ float ws[HH * HH], cf[HH], cms[HH];
    const int bx = blockIdx.x;
    const int b  = bx >> 3;
    const int rb = bx & 7;
    const int t  = threadIdx.x;
    const float* zin = selz(insel);
    float* zout = (outsel == 1) ? g_zA : g_zB;

    for (int i = t; i < HH * HH; i += 256) ws[i] = w[i];
    if (t < HH) cms[t] = g_colmax[b * HH + t];
    __syncthreads();

    if (t < HH) {
        float a0 = bias[t], a1 = 0.f, a2 = 0.f, a3 = 0.f;
#pragma unroll
        for (int h = 0; h < HH; h += 4) {
            a0 -= cms[h]     * ws[t * 64 + h];
            a1 -= cms[h + 1] * ws[t * 64 + h + 1];
            a2 -= cms[h + 2] * ws[t * 64 + h + 2];
            a3 -= cms[h + 3] * ws[t * 64 + h + 3];
        }
        cf[t] = (a0 + a1) + (a2 + a3);
    }
    __syncthreads();

    const int n = rb * 256 + t;
    if (n < NP) {
        const float* zr = &zin[((size_t)b * NP + n) * HH];
        float z[HH];
#pragma unroll
        for (int h = 0; h < HH; h++) z[h] = zr[h];
        float* orow = &zout[((size_t)b * NP + n) * HH];
#pragma unroll 4
        for (int fj = 0; fj < HH; fj++) {
            float a0 = cf[fj], a1 = 0.f, a2 = 0.f, a3 = 0.f;
#pragma unroll
            for (int h = 0; h < HH; h += 4) {
                a0 += z[h]     * ws[fj * 64 + h];
                a1 += z[h + 1] * ws[fj * 64 + h + 1];
                a2 += z[h + 2] * ws[fj * 64 + h + 2];
                a3 += z[h + 3] * ws[fj * 64 + h + 3];
            }
            orow[fj] = tanhf((a0 + a1) + (a2 + a3));
        }
    }
}

// ---------------- head: read precomputed colmax + 2-layer regressor + prior ----------------
__global__ __launch_bounds__(64) void k_head(
    const float* __restrict__ r1w, const float* __restrict__ r1b,
    const float* __restrict__ r2w, const float* __restrict__ r2b,
    float* __restrict__ out)
{
    const int b = blockIdx.x;
    const int f = threadIdx.x;
    __shared__ float s[HH], tv[HH];

    s[f] = g_colmax[b * HH + f];
    __syncthreads();

    float a = r1b[f];
#pragma unroll
    for (int h = 0; h < HH; h++) a += s[h] * r1w[f * 64 + h];
    tv[f] = tanhf(a);
    __syncthreads();

    if (f == 0) {
        float e = r2b[0];
        for (int h = 0; h < HH; h++) e += tv[h] * r2w[h];
        out[b] = e + (float)g_U0[b];
    }
}

// ---------------- launcher ----------------
extern "C" void kernel_launch(void* const* d_in, const int* in_sizes, int n_in,
                              void* d_out, int out_size)
{
    const float* pos = (const float*)d_in[0];
    const float* orR = (const float*)d_in[1];
    const int*   nbr = (const int*)  d_in[2];
    const float* w0  = (const float*)d_in[3];
    const float* b0  = (const float*)d_in[4];
    const float* w1  = (const float*)d_in[5];
    const float* b1  = (const float*)d_in[6];
    const float* g1  = (const float*)d_in[7];
    const float* be1 = (const float*)d_in[8];
    const float* w2  = (const float*)d_in[9];
    const float* b2  = (const float*)d_in[10];
    const float* g2  = (const float*)d_in[11];
    const float* be2 = (const float*)d_in[12];
    const float* w3  = (const float*)d_in[13];
    const float* b3  = (const float*)d_in[14];
    const float* p1w = (const float*)d_in[15];
    const float* p1b = (const float*)d_in[16];
    const float* p2w = (const float*)d_in[17];
    const float* p2b = (const float*)d_in[18];
    const float* p3w = (const float*)d_in[19];
    const float* p3b = (const float*)d_in[20];
    const float* r1w = (const float*)d_in[21];
    const float* r1b = (const float*)d_in[22];
    const float* r2w = (const float*)d_in[23];
    const float* r2b = (const float*)d_in[24];
    float* out = (float*)d_out;

    k_zero <<<1, 64>>>();
    k_edge1<<<NNODE, 64>>>(pos, orR, nbr, w0, b0, w1, b1);
    k_edge2<<<NNODE, 64>>>(g1, be1, w2, b2);
    k_edge3<<<NNODE, 64>>>(g2, be2, w3, b3);
    k_colmax<<<BB, 1024>>>(0);
    k_pe   <<<64, 256>>>(0, 1, p1w, p1b);
    k_colmax<<<BB, 1024>>>(1);
    k_pe   <<<64, 256>>>(1, 2, p2w, p2b);
    k_colmax<<<BB, 1024>>>(2);
    k_pe   <<<64, 256>>>(2, 1, p3w, p3b);
    k_colmax<<<BB, 1024>>>(1);
    k_head <<<BB, 64>>>(r1w, r1b, r2w, r2b, out);
}

// round 8
// speedup vs baseline: 2.0516x; 1.8193x over previous
#include <cuda_runtime.h>
#include <cuda_fp16.h>
#include <cuda_bf16.h>
#include <math.h>
#include <stdint.h>

#define BB   8
#define NP   2000
#define NNB  64
#define NF   19
#define HH   64
#define NNODE (BB*NP)          // 16000
#define NE   (BB*NP*NNB)       // 1024000
#define NCTA (NNODE/2)         // 8000 edge CTAs (2 nodes / 128 edges each)

// ---------------- device scratch ----------------
__device__ __half g_tbuf[(size_t)NE * HH];   // 131 MB, row-major [edge][j]
__device__ float  g_pooled[NNODE * HH];
__device__ float  g_zA[NNODE * HH];
__device__ float  g_zB[NNODE * HH];
__device__ float  g_colmax[BB * HH];
__device__ double g_sum1[HH], g_sq1[HH], g_sum2[HH], g_sq2[HH];
__device__ double g_U0[BB];

__device__ __forceinline__ const float* selz(int w) {
    return w == 0 ? g_pooled : (w == 1 ? g_zA : g_zB);
}

__device__ __forceinline__ uint32_t smem_u32(const void* p) {
    uint32_t a;
    asm("{ .reg .u64 t; cvta.to.shared.u64 t, %1; cvt.u32.u64 %0, t; }" : "=r"(a) : "l"(p));
    return a;
}

#define SW(o) ((o) ^ (((o) >> 3) & 0x70))

// ---- warp-level bf16 MMA (sm_80+ path, works at compute_100 base target) ----
#define MMA16816(c, a, br0, br1) \
    asm volatile("mma.sync.aligned.m16n8k16.row.col.f32.bf16.bf16.f32 " \
                 "{%0,%1,%2,%3}, {%4,%5,%6,%7}, {%8,%9}, {%0,%1,%2,%3};" \
                 : "+f"((c)[0]), "+f"((c)[1]), "+f"((c)[2]), "+f"((c)[3]) \
                 : "r"((a)[0]), "r"((a)[1]), "r"((a)[2]), "r"((a)[3]), \
                   "r"(br0), "r"(br1))

// A fragment: 16x16 tile at (m0, k0) of As[128][64bf16] rows 128B SW-swizzled
__device__ __forceinline__ void ldmA(uint32_t a[4], const unsigned char* As,
                                     int m0, int k0, int lane) {
    int row = m0 + (lane & 7) + ((lane & 8) ? 8 : 0);
    int kc  = k0 + ((lane & 16) ? 8 : 0);
    uint32_t addr = smem_u32(As + SW(row * 128 + kc * 2));
    asm volatile("ldmatrix.sync.aligned.m8n8.x4.shared.b16 {%0,%1,%2,%3}, [%4];"
                 : "=r"(a[0]), "=r"(a[1]), "=r"(a[2]), "=r"(a[3]) : "r"(addr));
}

// B fragments for two n-tiles (n0, n0+8), K-halves k0/k0+8, from Bs=W[j][k] rows 128B
__device__ __forceinline__ void ldmB(uint32_t b[4], const unsigned char* Bs,
                                     int n0, int k0, int lane) {
    int row = n0 + (lane & 7) + ((lane & 16) ? 8 : 0);
    int kc  = k0 + ((lane & 8) ? 8 : 0);
    uint32_t addr = smem_u32(Bs + SW(row * 128 + kc * 2));
    asm volatile("ldmatrix.sync.aligned.m8n8.x4.shared.b16 {%0,%1,%2,%3}, [%4];"
                 : "=r"(b[0]), "=r"(b[1]), "=r"(b[2]), "=r"(b[3]) : "r"(addr));
}

// full 128x64xK layer: warp wid computes rows [wid*32, wid*32+32)
template <int KS>
__device__ __forceinline__ void mma_layer(const unsigned char* As, const unsigned char* Bs,
                                          int wid, int lane, float c[2][8][4]) {
#pragma unroll
    for (int i = 0; i < 2; i++)
#pragma unroll
        for (int j = 0; j < 8; j++)
#pragma unroll
            for (int q = 0; q < 4; q++) c[i][j][q] = 0.f;
#pragma unroll
    for (int ks = 0; ks < KS; ks++) {
        int k0 = ks * 16;
        uint32_t a0[4], a1[4];
        ldmA(a0, As, wid * 32, k0, lane);
        ldmA(a1, As, wid * 32 + 16, k0, lane);
#pragma unroll
        for (int jt = 0; jt < 4; jt++) {
            uint32_t b[4];
            ldmB(b, Bs, jt * 16, k0, lane);
            MMA16816(c[0][jt * 2],     a0, b[0], b[1]);
            MMA16816(c[0][jt * 2 + 1], a0, b[2], b[3]);
            MMA16816(c[1][jt * 2],     a1, b[0], b[1]);
            MMA16816(c[1][jt * 2 + 1], a1, b[2], b[3]);
        }
    }
}

// ---------------- zero accumulators ----------------
__global__ void k_zero() {
    int t = threadIdx.x;
    if (t < HH) { g_sum1[t] = 0.0; g_sq1[t] = 0.0; g_sum2[t] = 0.0; g_sq2[t] = 0.0; }
    if (t < BB) g_U0[t] = 0.0;
}

// ---------------- stage 1: features -> MMA(W0) -> relu -> MMA(W1) -> stats, prior ----------------
__global__ __launch_bounds__(128, 4)
void k_edge1(const float* __restrict__ pos, const float* __restrict__ orR,
             const int* __restrict__ nbr,
             const float* __restrict__ w0, const float* __restrict__ b0,
             const float* __restrict__ w1, const float* __restrict__ b1)
{
    __shared__ __align__(128) unsigned char As[16384];
    __shared__ __align__(128) unsigned char Bs[8192];
    __shared__ __half2 stg[32 * 133];
    __shared__ float2 psum2[4 * 33], psq2[4 * 33];
    __shared__ float b0s[64], b1s[64], prsh[128];

    const int t = threadIdx.x, wid = t >> 5, lane = t & 31;
    const int cta = blockIdx.x;
    const int node0 = cta * 2;
    const int b = node0 / NP;

    if (t < 64) { b0s[t] = b0[t]; b1s[t] = b1[t]; }

    // B-tile: w0 zero-padded to K=32
    for (int idx = t; idx < 1024; idx += 128) {
        int j = idx >> 4, k2 = idx & 15;
        int c0 = 2 * k2, c1 = c0 + 1;
        float v0 = (c0 < NF) ? w0[j * NF + c0] : 0.f;
        float v1 = (c1 < NF) ? w0[j * NF + c1] : 0.f;
        *(__nv_bfloat162*)(Bs + SW(j * 128 + k2 * 4)) = __floats2bfloat162_rn(v0, v1);
    }

    // phase A: thread t = edge row t
    const int node = node0 + (t >> 6);
    const int m    = t & 63;
    const int jn   = nbr[node * NNB + m];
    const int nidx = b * NP + jn;

    float d0 = pos[nidx * 3 + 0] - pos[node * 3 + 0]; d0 -= rintf(d0);
    float d1 = pos[nidx * 3 + 1] - pos[node * 3 + 1]; d1 -= rintf(d1);
    float d2 = pos[nidx * 3 + 2] - pos[node * 3 + 2]; d2 -= rintf(d2);
    float r2 = d0 * d0 + d1 * d1 + d2 * d2 + 1e-12f;
    float R  = sqrtf(r2);
    float inv = 1.0f / R;

    float Ris[9], Rj[9];
#pragma unroll
    for (int k = 0; k < 9; k++) Ris[k] = orR[node * 9 + k];
#pragma unroll
    for (int k = 0; k < 9; k++) Rj[k]  = orR[nidx * 9 + k];

    float f[NF];
    f[0] = d0 * inv; f[1] = d1 * inv; f[2] = d2 * inv; f[3] = R;
#pragma unroll
    for (int j = 0; j < 3; j++) {
        f[4 + j] = f[0] * Ris[j] + f[1] * Ris[3 + j] + f[2] * Ris[6 + j];
        f[7 + j] = f[0] * Rj[j]  + f[1] * Rj[3 + j]  + f[2] * Rj[6 + j];
    }
#pragma unroll
    for (int j = 0; j < 3; j++)
#pragma unroll
        for (int k = 0; k < 3; k++)
            f[10 + j * 3 + k] = Ris[j] * Rj[k] + Ris[3 + j] * Rj[3 + k] + Ris[6 + j] * Rj[6 + k];

    {   // power-law prior (SIGMA/R)^12
        float tp = 0.01f * inv;
        float tp2 = tp * tp, tp4 = tp2 * tp2, tp8 = tp4 * tp4;
        prsh[t] = tp8 * tp4;
    }

    // A-tile row t: features bf16, cols 19..31 zero (only k<32 read in layer0)
#pragma unroll
    for (int j2 = 0; j2 < 16; j2++) {
        float v0 = 0.f, v1 = 0.f;
        if (j2 < 9) { v0 = f[2 * j2]; v1 = f[2 * j2 + 1]; }
        else if (j2 == 9) { v0 = f[18]; }
        *(__nv_bfloat162*)(As + SW(t * 128 + j2 * 4)) = __floats2bfloat162_rn(v0, v1);
    }
    __syncthreads();

    // layer 0: h1 = relu(X W0^T + b0)
    float c[2][8][4];
    mma_layer<2>(As, Bs, wid, lane, c);

    // epilogue 0: relu(+bias) -> As rows (own warp's rows only)
#pragma unroll
    for (int i = 0; i < 2; i++) {
        int r0 = wid * 32 + i * 16 + (lane >> 2);
#pragma unroll
        for (int j = 0; j < 8; j++) {
            int c0 = j * 8 + (lane & 3) * 2;
            float v00 = fmaxf(c[i][j][0] + b0s[c0],     0.f);
            float v01 = fmaxf(c[i][j][1] + b0s[c0 + 1], 0.f);
            float v10 = fmaxf(c[i][j][2] + b0s[c0],     0.f);
            float v11 = fmaxf(c[i][j][3] + b0s[c0 + 1], 0.f);
            *(__nv_bfloat162*)(As + SW(r0 * 128 + c0 * 2))       = __floats2bfloat162_rn(v00, v01);
            *(__nv_bfloat162*)(As + SW((r0 + 8) * 128 + c0 * 2)) = __floats2bfloat162_rn(v10, v11);
        }
    }
    __syncthreads();          // all warps done reading Bs(w0)

    for (int idx = t; idx < 2048; idx += 128) {
        int j = idx >> 5, k2 = idx & 31;
        *(__nv_bfloat162*)(Bs + SW(j * 128 + k2 * 4)) =
            __floats2bfloat162_rn(w1[j * 64 + 2 * k2], w1[j * 64 + 2 * k2 + 1]);
    }
    __syncthreads();

    // layer 1: t1 = h1 W1^T + b1
    mma_layer<4>(As, Bs, wid, lane, c);

    // epilogue 1: +bias, round fp16, stage for stats
#pragma unroll
    for (int i = 0; i < 2; i++) {
        int r0 = wid * 32 + i * 16 + (lane >> 2);
#pragma unroll
        for (int j = 0; j < 8; j++) {
            int c0 = j * 8 + (lane & 3) * 2;
            int jp = c0 >> 1;
            stg[jp * 133 + r0]     = __floats2half2_rn(c[i][j][0] + b1s[c0], c[i][j][1] + b1s[c0 + 1]);
            stg[jp * 133 + r0 + 8] = __floats2half2_rn(c[i][j][2] + b1s[c0], c[i][j][3] + b1s[c0 + 1]);
        }
    }
    __syncthreads();

    // global store: thread t writes row t (gather from stg columns)
    {
        __half2 o[32];
#pragma unroll
        for (int j2 = 0; j2 < 32; j2++) o[j2] = stg[j2 * 133 + t];
        __half* rowp = g_tbuf + ((size_t)cta * 128 + t) * 64;
#pragma unroll
        for (int q = 0; q < 8; q++) *(uint4*)(rowp + 8 * q) = ((uint4*)o)[q];
    }

    // stats reduce
    {
        int j2 = t & 31, rq = t >> 5;
        float s0 = 0, s1 = 0, q0 = 0, q1 = 0;
#pragma unroll 8
        for (int i = 0; i < 32; i++) {
            float2 v = __half22float2(stg[j2 * 133 + rq * 32 + i]);
            s0 += v.x; s1 += v.y; q0 += v.x * v.x; q1 += v.y * v.y;
        }
        psum2[rq * 33 + j2] = make_float2(s0, s1);
        psq2 [rq * 33 + j2] = make_float2(q0, q1);
    }
    __syncthreads();
    if (t < 64) {
        int j2 = t >> 1, comp = t & 1;
        float s = 0, q = 0;
#pragma unroll
        for (int rq = 0; rq < 4; rq++) {
            float2 a = psum2[rq * 33 + j2], c2 = psq2[rq * 33 + j2];
            s += comp ? a.y : a.x;
            q += comp ? c2.y : c2.x;
        }
        atomicAdd(&g_sum1[t], (double)s);
        atomicAdd(&g_sq1[t],  (double)q);
    }
    if (t == 0) {
        float ps = 0.f;
        for (int i = 0; i < 128; i++) ps += prsh[i];
        atomicAdd(&g_U0[b], (double)ps);
    }
}

// ---------------- stage 2: BN1+relu -> MMA(W2) -> stats ----------------
__global__ __launch_bounds__(128, 4)
void k_edge2(const float* __restrict__ g1, const float* __restrict__ be1,
             const float* __restrict__ w2, const float* __restrict__ b2)
{
    __shared__ __align__(128) unsigned char As[16384];
    __shared__ __align__(128) unsigned char Bs[8192];
    __shared__ __half2 stg[32 * 133];
    __shared__ float2 psum2[4 * 33], psq2[4 * 33];
    __shared__ float b2s[64], sc[64], sh[64];

    const int t = threadIdx.x, wid = t >> 5, lane = t & 31;
    const int cta = blockIdx.x;

    if (t < 64) {
        b2s[t] = b2[t];
        double mean = g_sum1[t] / (double)NE;
        double var  = g_sq1[t] / (double)NE - mean * mean;
        float istd  = rsqrtf((float)var + 1e-5f);
        float scale = g1[t] * istd;
        sc[t] = scale;
        sh[t] = be1[t] - (float)mean * scale;
    }
    for (int idx = t; idx < 2048; idx += 128) {
        int j = idx >> 5, k2 = idx & 31;
        *(__nv_bfloat162*)(Bs + SW(j * 128 + k2 * 4)) =
            __floats2bfloat162_rn(w2[j * 64 + 2 * k2], w2[j * 64 + 2 * k2 + 1]);
    }
    __syncthreads();
    {
        const __half2* rp = (const __half2*)(g_tbuf + ((size_t)cta * 128 + t) * 64);
#pragma unroll
        for (int j2 = 0; j2 < 32; j2++) {
            float2 v = __half22float2(rp[j2]);
            int j = 2 * j2;
            float h0 = fmaxf(v.x * sc[j]     + sh[j],     0.f);
            float h1 = fmaxf(v.y * sc[j + 1] + sh[j + 1], 0.f);
            *(__nv_bfloat162*)(As + SW(t * 128 + j2 * 4)) = __floats2bfloat162_rn(h0, h1);
        }
    }
    __syncthreads();

    float c[2][8][4];
    mma_layer<4>(As, Bs, wid, lane, c);

#pragma unroll
    for (int i = 0; i < 2; i++) {
        int r0 = wid * 32 + i * 16 + (lane >> 2);
#pragma unroll
        for (int j = 0; j < 8; j++) {
            int c0 = j * 8 + (lane & 3) * 2;
            int jp = c0 >> 1;
            stg[jp * 133 + r0]     = __floats2half2_rn(c[i][j][0] + b2s[c0], c[i][j][1] + b2s[c0 + 1]);
            stg[jp * 133 + r0 + 8] = __floats2half2_rn(c[i][j][2] + b2s[c0], c[i][j][3] + b2s[c0 + 1]);
        }
    }
    __syncthreads();

    {
        __half2 o[32];
#pragma unroll
        for (int j2 = 0; j2 < 32; j2++) o[j2] = stg[j2 * 133 + t];
        __half* rowp = g_tbuf + ((size_t)cta * 128 + t) * 64;
#pragma unroll
        for (int q = 0; q < 8; q++) *(uint4*)(rowp + 8 * q) = ((uint4*)o)[q];
    }
    {
        int j2 = t & 31, rq = t >> 5;
        float s0 = 0, s1 = 0, q0 = 0, q1 = 0;
#pragma unroll 8
        for (int i = 0; i < 32; i++) {
            float2 v = __half22float2(stg[j2 * 133 + rq * 32 + i]);
            s0 += v.x; s1 += v.y; q0 += v.x * v.x; q1 += v.y * v.y;
        }
        psum2[rq * 33 + j2] = make_float2(s0, s1);
        psq2 [rq * 33 + j2] = make_float2(q0, q1);
    }
    __syncthreads();
    if (t < 64) {
        int j2 = t >> 1, comp = t & 1;
        float s = 0, q = 0;
#pragma unroll
        for (int rq = 0; rq < 4; rq++) {
            float2 a = psum2[rq * 33 + j2], c2 = psq2[rq * 33 + j2];
            s += comp ? a.y : a.x;
            q += comp ? c2.y : c2.x;
        }
        atomicAdd(&g_sum2[t], (double)s);
        atomicAdd(&g_sq2[t],  (double)q);
    }
}

// ---------------- stage 3: BN2+relu -> MMA(W3) -> neighbor mean-pool ----------------
__global__ __launch_bounds__(128, 4)
void k_edge3(const float* __restrict__ g2, const float* __restrict__ be2,
             const float* __restrict__ w3, const float* __restrict__ b3)
{
    __shared__ __align__(128) unsigned char As[16384];
    __shared__ __align__(128) unsigned char Bs[8192];
    __shared__ __half2 stg[32 * 133];
    __shared__ float2 psum2[4 * 33];
    __shared__ float b3s[64], sc[64], sh[64];

    const int t = threadIdx.x, wid = t >> 5, lane = t & 31;
    const int cta = blockIdx.x;
    const int node0 = cta * 2;

    if (t < 64) {
        b3s[t] = b3[t];
        double mean = g_sum2[t] / (double)NE;
        double var  = g_sq2[t] / (double)NE - mean * mean;
        float istd  = rsqrtf((float)var + 1e-5f);
        float scale = g2[t] * istd;
        sc[t] = scale;
        sh[t] = be2[t] - (float)mean * scale;
    }
    for (int idx = t; idx < 2048; idx += 128) {
        int j = idx >> 5, k2 = idx & 31;
        *(__nv_bfloat162*)(Bs + SW(j * 128 + k2 * 4)) =
            __floats2bfloat162_rn(w3[j * 64 + 2 * k2], w3[j * 64 + 2 * k2 + 1]);
    }
    __syncthreads();
    {
        const __half2* rp = (const __half2*)(g_tbuf + ((size_t)cta * 128 + t) * 64);
#pragma unroll
        for (int j2 = 0; j2 < 32; j2++) {
            float2 v = __half22float2(rp[j2]);
            int j = 2 * j2;
            float h0 = fmaxf(v.x * sc[j]     + sh[j],     0.f);
            float h1 = fmaxf(v.y * sc[j + 1] + sh[j + 1], 0.f);
            *(__nv_bfloat162*)(As + SW(t * 128 + j2 * 4)) = __floats2bfloat162_rn(h0, h1);
        }
    }
    __syncthreads();

    float c[2][8][4];
    mma_layer<4>(As, Bs, wid, lane, c);

#pragma unroll
    for (int i = 0; i < 2; i++) {
        int r0 = wid * 32 + i * 16 + (lane >> 2);
#pragma unroll
        for (int j = 0; j < 8; j++) {
            int c0 = j * 8 + (lane & 3) * 2;
            int jp = c0 >> 1;
            stg[jp * 133 + r0]     = __floats2half2_rn(c[i][j][0], c[i][j][1]);
            stg[jp * 133 + r0 + 8] = __floats2half2_rn(c[i][j][2], c[i][j][3]);
        }
    }
    __syncthreads();
    {
        int j2 = t & 31, rq = t >> 5;
        float s0 = 0, s1 = 0;
#pragma unroll 8
        for (int i = 0; i < 32; i++) {
            float2 v = __half22float2(stg[j2 * 133 + rq * 32 + i]);
            s0 += v.x; s1 += v.y;
        }
        psum2[rq * 33 + j2] = make_float2(s0, s1);
    }
    __syncthreads();
    {
        int j = t & 63, j2 = j >> 1, comp = j & 1;
        int rqb = (t >> 6) * 2;                 // node select: rows 0-63 or 64-127
        float2 a = psum2[rqb * 33 + j2], c2 = psum2[(rqb + 1) * 33 + j2];
        float s = comp ? (a.y + c2.y) : (a.x + c2.x);
        g_pooled[(node0 + (t >> 6)) * HH + j] = s * (1.0f / NNB) + b3s[j];
    }
}

// ---------------- per-feature max over particles ----------------
__global__ __launch_bounds__(1024) void k_colmax(int insel)
{
    const float* z = selz(insel);
    const int b = blockIdx.x;
    const int t = threadIdx.x;
    const int f = t & 63, g = t >> 6;
    float mx = -INFINITY;
    for (int n = g; n < NP; n += 16)
        mx = fmaxf(mx, z[((size_t)b * NP + n) * HH + f]);
    __shared__ float red[1024];
    red[t] = mx;
    __syncthreads();
    if (g == 0) {
        float v = red[f];
#pragma unroll
        for (int r = 1; r < 16; r++) v = fmaxf(v, red[r * 64 + f]);
        g_colmax[b * HH + f] = v;
    }
}

// ---------------- PermEqui1_max: tanh((z - zmax) W^T + b) ----------------
__global__ __launch_bounds__(256) void k_pe(int insel, int outsel,
    const float* __restrict__ w, const float* __restrict__ bias)
{
    __shared__ float ws[HH * HH], cf[HH], cms[HH];
    const int bx = blockIdx.x;
    const int b  = bx >> 3;
    const int rb = bx & 7;
    const int t  = threadIdx.x;
    const float* zin = selz(insel);
    float* zout = (outsel == 1) ? g_zA : g_zB;

    for (int i = t; i < HH * HH; i += 256) ws[i] = w[i];
    if (t < HH) cms[t] = g_colmax[b * HH + t];
    __syncthreads();

    if (t < HH) {
        float a0 = bias[t], a1 = 0.f, a2 = 0.f, a3 = 0.f;
#pragma unroll
        for (int h = 0; h < HH; h += 4) {
            a0 -= cms[h]     * ws[t * 64 + h];
            a1 -= cms[h + 1] * ws[t * 64 + h + 1];
            a2 -= cms[h + 2] * ws[t * 64 + h + 2];
            a3 -= cms[h + 3] * ws[t * 64 + h + 3];
        }
        cf[t] = (a0 + a1) + (a2 + a3);
    }
    __syncthreads();

    const int n = rb * 256 + t;
    if (n < NP) {
        const float* zr = &zin[((size_t)b * NP + n) * HH];
        float z[HH];
#pragma unroll
        for (int h = 0; h < HH; h++) z[h] = zr[h];
        float* orow = &zout[((size_t)b * NP + n) * HH];
#pragma unroll 4
        for (int fj = 0; fj < HH; fj++) {
            float a0 = cf[fj], a1 = 0.f, a2 = 0.f, a3 = 0.f;
#pragma unroll
            for (int h = 0; h < HH; h += 4) {
                a0 += z[h]     * ws[fj * 64 + h];
                a1 += z[h + 1] * ws[fj * 64 + h + 1];
                a2 += z[h + 2] * ws[fj * 64 + h + 2];
                a3 += z[h + 3] * ws[fj * 64 + h + 3];
            }
            orow[fj] = tanhf((a0 + a1) + (a2 + a3));
        }
    }
}

// ---------------- head ----------------
__global__ __launch_bounds__(64) void k_head(
    const float* __restrict__ r1w, const float* __restrict__ r1b,
    const float* __restrict__ r2w, const float* __restrict__ r2b,
    float* __restrict__ out)
{
    const int b = blockIdx.x;
    const int f = threadIdx.x;
    __shared__ float s[HH], tv[HH];

    s[f] = g_colmax[b * HH + f];
    __syncthreads();

    float a = r1b[f];
#pragma unroll
    for (int h = 0; h < HH; h++) a += s[h] * r1w[f * 64 + h];
    tv[f] = tanhf(a);
    __syncthreads();

    if (f == 0) {
        float e = r2b[0];
        for (int h = 0; h < HH; h++) e += tv[h] * r2w[h];
        out[b] = e + (float)g_U0[b];
    }
}

// ---------------- launcher ----------------
extern "C" void kernel_launch(void* const* d_in, const int* in_sizes, int n_in,
                              void* d_out, int out_size)
{
    const float* pos = (const float*)d_in[0];
    const float* orR = (const float*)d_in[1];
    const int*   nbr = (const int*)  d_in[2];
    const float* w0  = (const float*)d_in[3];
    const float* b0  = (const float*)d_in[4];
    const float* w1  = (const float*)d_in[5];
    const float* b1  = (const float*)d_in[6];
    const float* g1  = (const float*)d_in[7];
    const float* be1 = (const float*)d_in[8];
    const float* w2  = (const float*)d_in[9];
    const float* b2  = (const float*)d_in[10];
    const float* g2  = (const float*)d_in[11];
    const float* be2 = (const float*)d_in[12];
    const float* w3  = (const float*)d_in[13];
    const float* b3  = (const float*)d_in[14];
    const float* p1w = (const float*)d_in[15];
    const float* p1b = (const float*)d_in[16];
    const float* p2w = (const float*)d_in[17];
    const float* p2b = (const float*)d_in[18];
    const float* p3w = (const float*)d_in[19];
    const float* p3b = (const float*)d_in[20];
    const float* r1w = (const float*)d_in[21];
    const float* r1b = (const float*)d_in[22];
    const float* r2w = (const float*)d_in[23];
    const float* r2b = (const float*)d_in[24];
    float* out = (float*)d_out;

    k_zero <<<1, 64>>>();
    k_edge1<<<NCTA, 128>>>(pos, orR, nbr, w0, b0, w1, b1);
    k_edge2<<<NCTA, 128>>>(g1, be1, w2, b2);
    k_edge3<<<NCTA, 128>>>(g2, be2, w3, b3);
    k_colmax<<<BB, 1024>>>(0);
    k_pe   <<<64, 256>>>(0, 1, p1w, p1b);
    k_colmax<<<BB, 1024>>>(1);
    k_pe   <<<64, 256>>>(1, 2, p2w, p2b);
    k_colmax<<<BB, 1024>>>(2);
    k_pe   <<<64, 256>>>(2, 1, p3w, p3b);
    k_colmax<<<BB, 1024>>>(1);
    k_head <<<BB, 64>>>(r1w, r1b, r2w, r2b, out);
}